// round 7
// baseline (speedup 1.0000x reference)
#include <cuda_runtime.h>
#include <cuda_bf16.h>
#include <math.h>

#define BATCH 32
#define NN 1024
#define MM 1024
#define TILES 8
#define NB (BATCH*TILES)      /* 256 CTAs */
#define NT 256
#define WARPS 8
#define TOL_F 1e-3f
#define MAX_ITER 50
#define CEXP (-28.853900817779268f)   /* -1/(0.05*ln2) : exp(-c/eps)=exp2(c*CEXP) */

// Scratch (__device__ globals — allocation-free per harness rules)
__device__ uint4   g_Kb[(size_t)BATCH*NN*MM/8];   // K in bf16, permuted row layout (64MB, L2-resident)
__device__ float   g_u[BATCH*NN];
__device__ float   g_v[BATCH*MM];
__device__ float   g_partial[(size_t)NB*MM];
__device__ unsigned g_change_bits = 0u;           // invariant: 0 at kernel entry (reset every col phase)
__device__ int      g_done = 0;                   // explicitly re-initialized at iter 0
__device__ unsigned g_bar_count = 0u;
__device__ unsigned g_bar_gen   = 0u;

// Sense-reversing grid barrier. Safe because all NB CTAs are co-resident
// (NB=256 <= 148 SMs * 2 CTAs/SM forced by __launch_bounds__(256,2) + 36KB smem).
__device__ __forceinline__ void grid_barrier() {
    __syncthreads();
    if (threadIdx.x == 0) {
        __threadfence();
        unsigned gen = *(volatile unsigned*)&g_bar_gen;
        if (atomicAdd(&g_bar_count, 1u) == NB - 1u) {
            g_bar_count = 0u;
            __threadfence();
            *(volatile unsigned*)&g_bar_gen = gen + 1u;
        } else {
            while (*(volatile unsigned*)&g_bar_gen == gen) __nanosleep(64);
        }
        __threadfence();
    }
    __syncthreads();
}

// Column mapping (chosen for conflict-free LDS of v):
// physical uint4 q = lane + 32*j of a row holds bf16 pairs p = 4*j+i (i=0..3),
// pair p of lane L covers true columns (2L + 64p, 2L + 64p + 1).
__global__ void __launch_bounds__(NT, 2)
sinkhorn_kernel(const float* __restrict__ cost, const float* __restrict__ src,
                const float* __restrict__ tgt, float* __restrict__ out)
{
    __shared__ float colacc[WARPS][MM];   // 32KB
    __shared__ float s_v[MM];             // 4KB
    __shared__ float s_cmax[WARPS];

    const int cta  = blockIdx.x;
    const int b    = cta >> 3;
    const int t    = cta & 7;
    const int tid  = threadIdx.x;
    const int warp = tid >> 5;
    const int lane = tid & 31;
    const int row0 = t*128 + warp*16;

    float prev_ln = 0.0f;    // lane r (r<16) holds previous log(u) of its warp's row r

    for (int it = 0; it < MAX_ITER; ++it) {
        if (it > 0) {
            if (*(volatile int*)&g_done) break;  // consistent: written before prior barrier
            for (int i = tid; i < MM/4; i += NT)
                ((float4*)s_v)[i] = __ldcg((const float4*)(g_v + b*MM) + i);
        }
        __syncthreads();

        float2 acc[4][4];
        #pragma unroll
        for (int j = 0; j < 4; j++)
            #pragma unroll
            for (int i = 0; i < 4; i++) acc[j][i] = make_float2(0.f, 0.f);
        float cmax = 0.f;

        if (it == 0) {
            // ---- iteration 0: compute K=exp2(cost*CEXP), round to bf16, store, and
            // ---- run the first row update with v = 1 (log_v0 = 0).
            const float* Crow = cost + ((size_t)b*NN + row0)*MM;
            uint4* Kw = g_Kb + ((size_t)b*NN + row0)*128 + lane;
            for (int r = 0; r < 16; ++r) {
                uint4 kq[4];
                float dot = 0.f;
                #pragma unroll
                for (int j = 0; j < 4; j++) {
                    union { uint4 q; __nv_bfloat162 h[4]; } U;
                    #pragma unroll
                    for (int i = 0; i < 4; i++) {
                        float2 c2 = *(const float2*)(Crow + 2*lane + 256*j + 64*i);
                        U.h[i] = __float22bfloat162_rn(
                            make_float2(exp2f(c2.x*CEXP), exp2f(c2.y*CEXP)));
                        float2 kr = __bfloat1622float2(U.h[i]);   // rounded value
                        dot += kr.x + kr.y;                        // v = 1
                    }
                    Kw[32*j] = U.q;
                    kq[j] = U.q;
                }
                #pragma unroll
                for (int o = 16; o; o >>= 1) dot += __shfl_xor_sync(0xffffffffu, dot, o);
                const int n = row0 + r;
                const float unew = (__ldg(src + b*NN + n) + 1e-12f) / dot;
                const float ln = logf(unew);
                if (lane == 0) g_u[b*NN + n] = unew;
                if (lane == r) { cmax = fmaxf(cmax, fabsf(ln - prev_ln)); prev_ln = ln; }
                #pragma unroll
                for (int j = 0; j < 4; j++) {
                    union { uint4 q; __nv_bfloat162 h[4]; } W; W.q = kq[j];
                    #pragma unroll
                    for (int i = 0; i < 4; i++) {
                        float2 kf = __bfloat1622float2(W.h[i]);
                        acc[j][i].x = fmaf(kf.x, unew, acc[j][i].x);
                        acc[j][i].y = fmaf(kf.y, unew, acc[j][i].y);
                    }
                }
                Crow += MM; Kw += 128;
            }
        } else {
            // ---- steady iterations: bf16 K from L2, double-buffered rows.
            const uint4* Krow = g_Kb + ((size_t)b*NN + row0)*128 + lane;
            uint4 k0[4];
            #pragma unroll
            for (int j = 0; j < 4; j++) k0[j] = Krow[32*j];
            for (int r = 0; r < 16; ++r) {
                const uint4* nxt = Krow + ((r < 15) ? 128 : 0);
                uint4 k1[4];
                #pragma unroll
                for (int j = 0; j < 4; j++) k1[j] = nxt[32*j];  // prefetch next row
                float dot = 0.f;
                #pragma unroll
                for (int j = 0; j < 4; j++) {
                    union { uint4 q; __nv_bfloat162 h[4]; } W; W.q = k0[j];
                    #pragma unroll
                    for (int i = 0; i < 4; i++) {
                        float2 kf = __bfloat1622float2(W.h[i]);
                        float2 vf = *(const float2*)(s_v + 2*lane + 256*j + 64*i);
                        dot = fmaf(kf.x, vf.x, dot);
                        dot = fmaf(kf.y, vf.y, dot);
                    }
                }
                #pragma unroll
                for (int o = 16; o; o >>= 1) dot += __shfl_xor_sync(0xffffffffu, dot, o);
                const int n = row0 + r;
                const float unew = (__ldg(src + b*NN + n) + 1e-12f) / dot;
                const float ln = logf(unew);
                if (lane == 0) g_u[b*NN + n] = unew;
                if (lane == r) { cmax = fmaxf(cmax, fabsf(ln - prev_ln)); prev_ln = ln; }
                #pragma unroll
                for (int j = 0; j < 4; j++) {
                    union { uint4 q; __nv_bfloat162 h[4]; } W; W.q = k0[j];
                    #pragma unroll
                    for (int i = 0; i < 4; i++) {
                        float2 kf = __bfloat1622float2(W.h[i]);
                        acc[j][i].x = fmaf(kf.x, unew, acc[j][i].x);
                        acc[j][i].y = fmaf(kf.y, unew, acc[j][i].y);
                    }
                }
                #pragma unroll
                for (int j = 0; j < 4; j++) k0[j] = k1[j];
                Krow += 128;
            }
        }

        // ---- dump warp column-accumulators (true column index = 2*lane + 64*(4j+i))
        #pragma unroll
        for (int j = 0; j < 4; j++)
            #pragma unroll
            for (int i = 0; i < 4; i++)
                *(float2*)&colacc[warp][2*lane + 256*j + 64*i] = acc[j][i];
        #pragma unroll
        for (int o = 16; o; o >>= 1) cmax = fmaxf(cmax, __shfl_xor_sync(0xffffffffu, cmax, o));
        if (lane == 0) s_cmax[warp] = cmax;
        __syncthreads();

        {   // fixed-order cross-warp reduce -> per-tile column partials
            const int m0 = tid*4;
            float4 s = *(const float4*)&colacc[0][m0];
            #pragma unroll
            for (int w = 1; w < WARPS; w++) {
                float4 a = *(const float4*)&colacc[w][m0];
                s.x += a.x; s.y += a.y; s.z += a.z; s.w += a.w;
            }
            *(float4*)&g_partial[(size_t)cta*MM + m0] = s;
        }
        if (tid == 0) {
            float cm = s_cmax[0];
            #pragma unroll
            for (int w = 1; w < WARPS; w++) cm = fmaxf(cm, s_cmax[w]);
            atomicMax(&g_change_bits, __float_as_uint(cm));  // order-independent
        }

        grid_barrier();

        // ---- column phase: each CTA reduces one 128-col segment of one batch
        if (tid < 32) {
            const int b2 = cta >> 3;
            const int m0 = (cta & 7)*128 + tid*4;
            const float* P = g_partial + (size_t)b2*TILES*MM;
            float4 s = __ldcg((const float4*)(P + m0));
            #pragma unroll
            for (int tt = 1; tt < TILES; tt++) {
                float4 a = __ldcg((const float4*)(P + (size_t)tt*MM + m0));
                s.x += a.x; s.y += a.y; s.z += a.z; s.w += a.w;
            }
            const float4 c = *(const float4*)(tgt + b2*MM + m0);
            float4 v;
            v.x = (c.x + 1e-12f)/s.x; v.y = (c.y + 1e-12f)/s.y;
            v.z = (c.z + 1e-12f)/s.z; v.w = (c.w + 1e-12f)/s.w;
            *(float4*)(g_v + b2*MM + m0) = v;
        }
        if (cta == 0 && tid == 0) {
            unsigned ch = *(volatile unsigned*)&g_change_bits;
            const int d = (__uint_as_float(ch) < TOL_F) ? 1 : 0;
            if (it == 0) g_done = d;          // also clears stale flag from prior run
            else if (d)  g_done = 1;
            g_change_bits = 0u;
        }

        grid_barrier();
    }

    // ---- output: T[b,n,m] = u[b,n] * exp2(cost*CEXP) * v[b,m]  (exact fp32 K)
    {
        const size_t TOT4 = (size_t)BATCH*NN*MM/4;
        const float4* c4 = (const float4*)cost;
        float4* o4 = (float4*)out;
        #pragma unroll 4
        for (size_t i = (size_t)cta*NT + tid; i < TOT4; i += (size_t)NB*NT) {
            const size_t e = i << 2;
            const int bb = (int)(e >> 20);
            const int n  = (int)((e >> 10) & 1023);
            const int m  = (int)(e & 1023);
            const float  u = __ldcg(g_u + bb*NN + n);
            const float4 v = __ldcg((const float4*)(g_v + bb*MM + m));
            const float4 c = c4[i];
            float4 o;
            o.x = u*exp2f(c.x*CEXP)*v.x;
            o.y = u*exp2f(c.y*CEXP)*v.y;
            o.z = u*exp2f(c.z*CEXP)*v.z;
            o.w = u*exp2f(c.w*CEXP)*v.w;
            o4[i] = o;
        }
    }
}

extern "C" void kernel_launch(void* const* d_in, const int* in_sizes, int n_in,
                              void* d_out, int out_size) {
    const float* cost = (const float*)d_in[0];
    const float* src  = (const float*)d_in[1];
    const float* tgt  = (const float*)d_in[2];
    (void)in_sizes; (void)n_in; (void)out_size;
    sinkhorn_kernel<<<NB, NT>>>(cost, src, tgt, (float*)d_out);
}

// round 8
// speedup vs baseline: 1.0249x; 1.0249x over previous
#include <cuda_runtime.h>
#include <cuda_bf16.h>
#include <math.h>

#define BATCH 32
#define NN 1024
#define MM 1024
#define TILES 8
#define NB (BATCH*TILES)      /* 256 CTAs */
#define NT 256
#define WARPS 8
#define TOL_F 1e-3f
#define MAX_ITER 50
#define CEXP (-28.853900817779268f)   /* -1/(0.05*ln2) : exp(-c/eps)=exp2(c*CEXP) */

// Scratch (__device__ globals — allocation-free per harness rules)
__device__ uint4   g_Kb[(size_t)BATCH*NN*MM/8];   // K in bf16, permuted row layout (64MB, L2-resident)
__device__ float   g_u[BATCH*NN];
__device__ float   g_v[BATCH*MM];
__device__ float   g_partial[(size_t)NB*MM];
__device__ unsigned g_change_bits = 0u;           // invariant: 0 at kernel entry (reset every col phase)
__device__ int      g_done = 0;                   // explicitly re-initialized at iter 0
__device__ unsigned g_bar_count = 0u;
__device__ unsigned g_bar_gen   = 0u;

// Sense-reversing grid barrier. Safe because all NB CTAs are co-resident
// (NB=256 <= 148 SMs * 2 CTAs/SM forced by __launch_bounds__(256,2) + 36KB smem).
__device__ __forceinline__ void grid_barrier() {
    __syncthreads();
    if (threadIdx.x == 0) {
        __threadfence();
        unsigned gen = *(volatile unsigned*)&g_bar_gen;
        if (atomicAdd(&g_bar_count, 1u) == NB - 1u) {
            g_bar_count = 0u;
            __threadfence();
            *(volatile unsigned*)&g_bar_gen = gen + 1u;
        } else {
            while (*(volatile unsigned*)&g_bar_gen == gen) __nanosleep(64);
        }
        __threadfence();
    }
    __syncthreads();
}

// Column mapping (chosen for conflict-free LDS of v):
// physical uint4 q = lane + 32*j of a row holds bf16 pairs p = 4*j+i (i=0..3),
// pair p of lane L covers true columns (2L + 64p, 2L + 64p + 1).
__global__ void __launch_bounds__(NT, 2)
sinkhorn_kernel(const float* __restrict__ cost, const float* __restrict__ src,
                const float* __restrict__ tgt, float* __restrict__ out)
{
    __shared__ float colacc[WARPS][MM];   // 32KB
    __shared__ float s_v[MM];             // 4KB
    __shared__ float s_cmax[WARPS];

    const int cta  = blockIdx.x;
    const int b    = cta >> 3;
    const int t    = cta & 7;
    const int tid  = threadIdx.x;
    const int warp = tid >> 5;
    const int lane = tid & 31;
    const int row0 = t*128 + warp*16;

    float prev_ln = 0.0f;    // lane r (r<16) holds previous log(u) of its warp's row r

    for (int it = 0; it < MAX_ITER; ++it) {
        if (it > 0) {
            if (*(volatile int*)&g_done) break;  // consistent: written before prior barrier
            for (int i = tid; i < MM/4; i += NT)
                ((float4*)s_v)[i] = __ldcg((const float4*)(g_v + b*MM) + i);
        }
        __syncthreads();

        float2 acc[4][4];
        #pragma unroll
        for (int j = 0; j < 4; j++)
            #pragma unroll
            for (int i = 0; i < 4; i++) acc[j][i] = make_float2(0.f, 0.f);
        float cmax = 0.f;

        if (it == 0) {
            // ---- iteration 0: compute K=exp2(cost*CEXP), round to bf16, store, and
            // ---- run the first row update with v = 1 (log_v0 = 0).
            const float* Crow = cost + ((size_t)b*NN + row0)*MM;
            uint4* Kw = g_Kb + ((size_t)b*NN + row0)*128 + lane;
            for (int r = 0; r < 16; ++r) {
                uint4 kq[4];
                float dot = 0.f;
                #pragma unroll
                for (int j = 0; j < 4; j++) {
                    union { uint4 q; __nv_bfloat162 h[4]; } U;
                    #pragma unroll
                    for (int i = 0; i < 4; i++) {
                        float2 c2 = *(const float2*)(Crow + 2*lane + 256*j + 64*i);
                        U.h[i] = __float22bfloat162_rn(
                            make_float2(exp2f(c2.x*CEXP), exp2f(c2.y*CEXP)));
                        float2 kr = __bfloat1622float2(U.h[i]);   // rounded value
                        dot += kr.x + kr.y;                        // v = 1
                    }
                    Kw[32*j] = U.q;
                    kq[j] = U.q;
                }
                #pragma unroll
                for (int o = 16; o; o >>= 1) dot += __shfl_xor_sync(0xffffffffu, dot, o);
                const int n = row0 + r;
                const float unew = (__ldg(src + b*NN + n) + 1e-12f) / dot;
                const float ln = logf(unew);
                if (lane == 0) g_u[b*NN + n] = unew;
                if (lane == r) { cmax = fmaxf(cmax, fabsf(ln - prev_ln)); prev_ln = ln; }
                #pragma unroll
                for (int j = 0; j < 4; j++) {
                    union { uint4 q; __nv_bfloat162 h[4]; } W; W.q = kq[j];
                    #pragma unroll
                    for (int i = 0; i < 4; i++) {
                        float2 kf = __bfloat1622float2(W.h[i]);
                        acc[j][i].x = fmaf(kf.x, unew, acc[j][i].x);
                        acc[j][i].y = fmaf(kf.y, unew, acc[j][i].y);
                    }
                }
                Crow += MM; Kw += 128;
            }
        } else {
            // ---- steady iterations: bf16 K from L2, double-buffered rows.
            const uint4* Krow = g_Kb + ((size_t)b*NN + row0)*128 + lane;
            uint4 k0[4];
            #pragma unroll
            for (int j = 0; j < 4; j++) k0[j] = Krow[32*j];
            for (int r = 0; r < 16; ++r) {
                const uint4* nxt = Krow + ((r < 15) ? 128 : 0);
                uint4 k1[4];
                #pragma unroll
                for (int j = 0; j < 4; j++) k1[j] = nxt[32*j];  // prefetch next row
                float dot = 0.f;
                #pragma unroll
                for (int j = 0; j < 4; j++) {
                    union { uint4 q; __nv_bfloat162 h[4]; } W; W.q = k0[j];
                    #pragma unroll
                    for (int i = 0; i < 4; i++) {
                        float2 kf = __bfloat1622float2(W.h[i]);
                        float2 vf = *(const float2*)(s_v + 2*lane + 256*j + 64*i);
                        dot = fmaf(kf.x, vf.x, dot);
                        dot = fmaf(kf.y, vf.y, dot);
                    }
                }
                #pragma unroll
                for (int o = 16; o; o >>= 1) dot += __shfl_xor_sync(0xffffffffu, dot, o);
                const int n = row0 + r;
                const float unew = (__ldg(src + b*NN + n) + 1e-12f) / dot;
                const float ln = logf(unew);
                if (lane == 0) g_u[b*NN + n] = unew;
                if (lane == r) { cmax = fmaxf(cmax, fabsf(ln - prev_ln)); prev_ln = ln; }
                #pragma unroll
                for (int j = 0; j < 4; j++) {
                    union { uint4 q; __nv_bfloat162 h[4]; } W; W.q = k0[j];
                    #pragma unroll
                    for (int i = 0; i < 4; i++) {
                        float2 kf = __bfloat1622float2(W.h[i]);
                        acc[j][i].x = fmaf(kf.x, unew, acc[j][i].x);
                        acc[j][i].y = fmaf(kf.y, unew, acc[j][i].y);
                    }
                }
                #pragma unroll
                for (int j = 0; j < 4; j++) k0[j] = k1[j];
                Krow += 128;
            }
        }

        // ---- dump warp column-accumulators (true column index = 2*lane + 64*(4j+i))
        #pragma unroll
        for (int j = 0; j < 4; j++)
            #pragma unroll
            for (int i = 0; i < 4; i++)
                *(float2*)&colacc[warp][2*lane + 256*j + 64*i] = acc[j][i];
        #pragma unroll
        for (int o = 16; o; o >>= 1) cmax = fmaxf(cmax, __shfl_xor_sync(0xffffffffu, cmax, o));
        if (lane == 0) s_cmax[warp] = cmax;
        __syncthreads();

        {   // fixed-order cross-warp reduce -> per-tile column partials
            const int m0 = tid*4;
            float4 s = *(const float4*)&colacc[0][m0];
            #pragma unroll
            for (int w = 1; w < WARPS; w++) {
                float4 a = *(const float4*)&colacc[w][m0];
                s.x += a.x; s.y += a.y; s.z += a.z; s.w += a.w;
            }
            *(float4*)&g_partial[(size_t)cta*MM + m0] = s;
        }
        if (tid == 0) {
            float cm = s_cmax[0];
            #pragma unroll
            for (int w = 1; w < WARPS; w++) cm = fmaxf(cm, s_cmax[w]);
            atomicMax(&g_change_bits, __float_as_uint(cm));  // order-independent
        }

        grid_barrier();

        // ---- column phase: each CTA reduces one 128-col segment of one batch
        if (tid < 32) {
            const int b2 = cta >> 3;
            const int m0 = (cta & 7)*128 + tid*4;
            const float* P = g_partial + (size_t)b2*TILES*MM;
            float4 s = __ldcg((const float4*)(P + m0));
            #pragma unroll
            for (int tt = 1; tt < TILES; tt++) {
                float4 a = __ldcg((const float4*)(P + (size_t)tt*MM + m0));
                s.x += a.x; s.y += a.y; s.z += a.z; s.w += a.w;
            }
            const float4 c = *(const float4*)(tgt + b2*MM + m0);
            float4 v;
            v.x = (c.x + 1e-12f)/s.x; v.y = (c.y + 1e-12f)/s.y;
            v.z = (c.z + 1e-12f)/s.z; v.w = (c.w + 1e-12f)/s.w;
            *(float4*)(g_v + b2*MM + m0) = v;
        }
        if (cta == 0 && tid == 0) {
            unsigned ch = *(volatile unsigned*)&g_change_bits;
            const int d = (__uint_as_float(ch) < TOL_F) ? 1 : 0;
            if (it == 0) g_done = d;          // also clears stale flag from prior run
            else if (d)  g_done = 1;
            g_change_bits = 0u;
        }

        grid_barrier();
    }

    // ---- output: T[b,n,m] = u[b,n] * exp2(cost*CEXP) * v[b,m]  (exact fp32 K)
    {
        const size_t TOT4 = (size_t)BATCH*NN*MM/4;
        const float4* c4 = (const float4*)cost;
        float4* o4 = (float4*)out;
        #pragma unroll 4
        for (size_t i = (size_t)cta*NT + tid; i < TOT4; i += (size_t)NB*NT) {
            const size_t e = i << 2;
            const int bb = (int)(e >> 20);
            const int n  = (int)((e >> 10) & 1023);
            const int m  = (int)(e & 1023);
            const float  u = __ldcg(g_u + bb*NN + n);
            const float4 v = __ldcg((const float4*)(g_v + bb*MM + m));
            const float4 c = c4[i];
            float4 o;
            o.x = u*exp2f(c.x*CEXP)*v.x;
            o.y = u*exp2f(c.y*CEXP)*v.y;
            o.z = u*exp2f(c.z*CEXP)*v.z;
            o.w = u*exp2f(c.w*CEXP)*v.w;
            o4[i] = o;
        }
    }
}

extern "C" void kernel_launch(void* const* d_in, const int* in_sizes, int n_in,
                              void* d_out, int out_size) {
    const float* cost = (const float*)d_in[0];
    const float* src  = (const float*)d_in[1];
    const float* tgt  = (const float*)d_in[2];
    (void)in_sizes; (void)n_in; (void)out_size;
    sinkhorn_kernel<<<NB, NT>>>(cost, src, tgt, (float*)d_out);
}